// round 3
// baseline (speedup 1.0000x reference)
#include <cuda_runtime.h>
#include <math.h>

// Problem constants (fixed by the benchmark shapes)
#define T_TOK 4096   // B*S tokens
#define D_DIM 1024   // embed dim
#define U_DIM 4096   // ffn dim
#define E_NUM 8      // experts
#define TOPK  2

// ---------------- scratch (static device globals; no allocation) ----------
// H activations for all routed (token, expert) pairs: 8192 * 4096 floats = 134MB
__device__ float g_H[(size_t)T_TOK * TOPK * U_DIM];
__device__ int   g_tok[E_NUM * T_TOK];   // per-expert compact token list
__device__ float g_wt [E_NUM * T_TOK];   // matching router weights
__device__ int   g_cnt[E_NUM];
__device__ int   g_off[E_NUM];

// ---------------- router ---------------------------------------------------
__global__ void zero_cnt_kernel() {
    if (threadIdx.x < E_NUM) g_cnt[threadIdx.x] = 0;
}

__global__ void router_kernel(const float* __restrict__ x,
                              const float* __restrict__ wr) {
    int t    = blockIdx.x * 4 + (threadIdx.x >> 5);   // warp per token
    int lane = threadIdx.x & 31;
    if (t >= T_TOK) return;
    const float* xr = x + (size_t)t * D_DIM;

    float logit[E_NUM];
#pragma unroll
    for (int e = 0; e < E_NUM; e++) {
        const float* w = wr + e * D_DIM;
        float s = 0.f;
        for (int i = lane; i < D_DIM; i += 32)
            s += xr[i] * w[i];
#pragma unroll
        for (int o = 16; o > 0; o >>= 1)
            s += __shfl_xor_sync(0xffffffffu, s, o);
        logit[e] = s;
    }

    if (lane == 0) {
        // top-2 (first-occurrence tie-break, matching lax.top_k)
        int e0 = 0; float l0 = logit[0];
#pragma unroll
        for (int e = 1; e < E_NUM; e++)
            if (logit[e] > l0) { l0 = logit[e]; e0 = e; }
        int e1 = -1; float l1 = -INFINITY;
#pragma unroll
        for (int e = 0; e < E_NUM; e++)
            if (e != e0 && logit[e] > l1) { l1 = logit[e]; e1 = e; }

        // softmax over the two top logits (l0 >= l1)
        float p1 = expf(l1 - l0);
        float inv = 1.f / (1.f + p1);
        float w0 = inv, w1 = p1 * inv;

        int p;
        p = atomicAdd(&g_cnt[e0], 1);
        g_tok[e0 * T_TOK + p] = t;  g_wt[e0 * T_TOK + p] = w0;
        p = atomicAdd(&g_cnt[e1], 1);
        g_tok[e1 * T_TOK + p] = t;  g_wt[e1 * T_TOK + p] = w1;
    }
}

__global__ void offsets_kernel() {
    if (threadIdx.x == 0) {
        int acc = 0;
#pragma unroll
        for (int e = 0; e < E_NUM; e++) { g_off[e] = acc; acc += g_cnt[e]; }
    }
}

// ---------------- grouped GEMMs (128x128x8 tile, 8x8 per thread) -----------
// C[m,n] = sum_k A[m,k]*B[n,k]   (both operands K-contiguous, row-major)

__global__ __launch_bounds__(256)
void up_kernel(const float* __restrict__ x,
               const float* __restrict__ w_up,
               const float* __restrict__ b_up) {
    int e   = blockIdx.z;
    int n_e = g_cnt[e];
    int m0  = blockIdx.y * 128;
    if (m0 >= n_e) return;
    int n0  = blockIdx.x * 128;

    const float* W = w_up + (size_t)e * U_DIM * D_DIM;

    __shared__ float As[8][128];
    __shared__ float Bs[8][128];

    int tid  = threadIdx.x;
    int lrow = tid >> 1;            // 0..127
    int lk   = (tid & 1) * 4;       // 0 or 4

    int  grow   = m0 + lrow;
    bool avalid = grow < n_e;
    int  tok    = avalid ? g_tok[e * T_TOK + grow] : 0;
    const float* arow = x + (size_t)tok * D_DIM;
    const float* brow = W + (size_t)(n0 + lrow) * D_DIM;

    float acc[8][8] = {};
    int tr = (tid >> 4) * 8;        // 0..120
    int tc = (tid & 15) * 8;        // 0..120

    for (int k0 = 0; k0 < D_DIM; k0 += 8) {
        float4 av = avalid ? *(const float4*)(arow + k0 + lk)
                           : make_float4(0.f, 0.f, 0.f, 0.f);
        float4 bv = *(const float4*)(brow + k0 + lk);
        __syncthreads();
        As[lk + 0][lrow] = av.x; As[lk + 1][lrow] = av.y;
        As[lk + 2][lrow] = av.z; As[lk + 3][lrow] = av.w;
        Bs[lk + 0][lrow] = bv.x; Bs[lk + 1][lrow] = bv.y;
        Bs[lk + 2][lrow] = bv.z; Bs[lk + 3][lrow] = bv.w;
        __syncthreads();
#pragma unroll
        for (int k = 0; k < 8; k++) {
            float a[8], b[8];
#pragma unroll
            for (int i = 0; i < 8; i++) a[i] = As[k][tr + i];
#pragma unroll
            for (int j = 0; j < 8; j++) b[j] = Bs[k][tc + j];
#pragma unroll
            for (int i = 0; i < 8; i++)
#pragma unroll
                for (int j = 0; j < 8; j++)
                    acc[i][j] += a[i] * b[j];
        }
    }

    // epilogue: bias + exact GELU -> H scratch
    int off = g_off[e];
    const float* bu = b_up + e * U_DIM;
#pragma unroll
    for (int i = 0; i < 8; i++) {
        int m = tr + i;
        if (m0 + m < n_e) {
            float* hp = g_H + (size_t)(off + m0 + m) * U_DIM + n0;
#pragma unroll
            for (int j = 0; j < 8; j++) {
                float v = acc[i][j] + bu[n0 + tc + j];
                v = 0.5f * v * (1.f + erff(v * 0.70710678118654752f));
                hp[tc + j] = v;
            }
        }
    }
}

__global__ __launch_bounds__(256)
void down_kernel(const float* __restrict__ w_down,
                 const float* __restrict__ b_down,
                 float* __restrict__ out) {
    int e   = blockIdx.z;
    int n_e = g_cnt[e];
    int m0  = blockIdx.y * 128;
    if (m0 >= n_e) return;
    int n0  = blockIdx.x * 128;
    int off = g_off[e];

    const float* W = w_down + (size_t)e * D_DIM * U_DIM;

    __shared__ float As[8][128];
    __shared__ float Bs[8][128];

    int tid  = threadIdx.x;
    int lrow = tid >> 1;
    int lk   = (tid & 1) * 4;

    int  grow   = m0 + lrow;
    bool avalid = grow < n_e;
    const float* arow = g_H + (size_t)(off + (avalid ? grow : 0)) * U_DIM;
    const float* brow = W + (size_t)(n0 + lrow) * U_DIM;

    float acc[8][8] = {};
    int tr = (tid >> 4) * 8;
    int tc = (tid & 15) * 8;

    for (int k0 = 0; k0 < U_DIM; k0 += 8) {
        float4 av = avalid ? *(const float4*)(arow + k0 + lk)
                           : make_float4(0.f, 0.f, 0.f, 0.f);
        float4 bv = *(const float4*)(brow + k0 + lk);
        __syncthreads();
        As[lk + 0][lrow] = av.x; As[lk + 1][lrow] = av.y;
        As[lk + 2][lrow] = av.z; As[lk + 3][lrow] = av.w;
        Bs[lk + 0][lrow] = bv.x; Bs[lk + 1][lrow] = bv.y;
        Bs[lk + 2][lrow] = bv.z; Bs[lk + 3][lrow] = bv.w;
        __syncthreads();
#pragma unroll
        for (int k = 0; k < 8; k++) {
            float a[8], b[8];
#pragma unroll
            for (int i = 0; i < 8; i++) a[i] = As[k][tr + i];
#pragma unroll
            for (int j = 0; j < 8; j++) b[j] = Bs[k][tc + j];
#pragma unroll
            for (int i = 0; i < 8; i++)
#pragma unroll
                for (int j = 0; j < 8; j++)
                    acc[i][j] += a[i] * b[j];
        }
    }

    // epilogue: bias, router weight, scatter-add into out
    const float* bd = b_down + e * D_DIM;
#pragma unroll
    for (int i = 0; i < 8; i++) {
        int m = tr + i;
        if (m0 + m < n_e) {
            int   tok = g_tok[e * T_TOK + m0 + m];
            float wgt = g_wt [e * T_TOK + m0 + m];
            float* op = out + (size_t)tok * D_DIM + n0;
#pragma unroll
            for (int j = 0; j < 8; j++) {
                float v = wgt * (acc[i][j] + bd[n0 + tc + j]);
                atomicAdd(&op[tc + j], v);
            }
        }
    }
}

// ---------------- launch ----------------------------------------------------
extern "C" void kernel_launch(void* const* d_in, const int* in_sizes, int n_in,
                              void* d_out, int out_size) {
    const float* x  = (const float*)d_in[0];
    const float* wr = (const float*)d_in[1];
    const float* wu = (const float*)d_in[2];
    const float* bu = (const float*)d_in[3];
    const float* wd = (const float*)d_in[4];
    const float* bd = (const float*)d_in[5];
    float* out = (float*)d_out;

    cudaMemsetAsync(out, 0, (size_t)out_size * sizeof(float), 0);
    zero_cnt_kernel<<<1, 32>>>();
    router_kernel<<<T_TOK / 4, 128>>>(x, wr);
    offsets_kernel<<<1, 32>>>();

    dim3 gu(U_DIM / 128, T_TOK / 128, E_NUM);   // (32, 32, 8), inactive tiles exit fast
    up_kernel<<<gu, 256>>>(x, wu, bu);

    dim3 gd(D_DIM / 128, T_TOK / 128, E_NUM);   // (8, 32, 8)
    down_kernel<<<gd, 256>>>(wd, bd, out);
}

// round 5
// speedup vs baseline: 1.0014x; 1.0014x over previous
#include <cuda_runtime.h>
#include <math.h>

// Problem constants (fixed by the benchmark shapes)
#define T_TOK 4096   // B*S tokens
#define D_DIM 1024   // embed dim
#define U_DIM 4096   // ffn dim
#define E_NUM 8      // experts
#define TOPK  2

// ---------------- scratch (static device globals; no allocation) ----------
// H activations for all routed (token, expert) pairs: 8192 * 4096 floats = 134MB
__device__ float g_H[(size_t)T_TOK * TOPK * U_DIM];
__device__ int   g_tok[E_NUM * T_TOK];   // per-expert compact token list
__device__ float g_wt [E_NUM * T_TOK];   // matching router weights
__device__ int   g_cnt[E_NUM];
__device__ int   g_off[E_NUM];

// ---------------- router ---------------------------------------------------
__global__ void zero_cnt_kernel() {
    if (threadIdx.x < E_NUM) g_cnt[threadIdx.x] = 0;
}

__global__ void router_kernel(const float* __restrict__ x,
                              const float* __restrict__ wr) {
    int t    = blockIdx.x * 4 + (threadIdx.x >> 5);   // warp per token
    int lane = threadIdx.x & 31;
    if (t >= T_TOK) return;
    const float* xr = x + (size_t)t * D_DIM;

    float logit[E_NUM];
#pragma unroll
    for (int e = 0; e < E_NUM; e++) {
        const float* w = wr + e * D_DIM;
        float s = 0.f;
        for (int i = lane; i < D_DIM; i += 32)
            s += xr[i] * w[i];
#pragma unroll
        for (int o = 16; o > 0; o >>= 1)
            s += __shfl_xor_sync(0xffffffffu, s, o);
        logit[e] = s;
    }

    if (lane == 0) {
        // top-2 (first-occurrence tie-break, matching lax.top_k)
        int e0 = 0; float l0 = logit[0];
#pragma unroll
        for (int e = 1; e < E_NUM; e++)
            if (logit[e] > l0) { l0 = logit[e]; e0 = e; }
        int e1 = -1; float l1 = -INFINITY;
#pragma unroll
        for (int e = 0; e < E_NUM; e++)
            if (e != e0 && logit[e] > l1) { l1 = logit[e]; e1 = e; }

        // softmax over the two top logits (l0 >= l1)
        float p1 = expf(l1 - l0);
        float inv = 1.f / (1.f + p1);
        float w0 = inv, w1 = p1 * inv;

        int p;
        p = atomicAdd(&g_cnt[e0], 1);
        g_tok[e0 * T_TOK + p] = t;  g_wt[e0 * T_TOK + p] = w0;
        p = atomicAdd(&g_cnt[e1], 1);
        g_tok[e1 * T_TOK + p] = t;  g_wt[e1 * T_TOK + p] = w1;
    }
}

__global__ void offsets_kernel() {
    if (threadIdx.x == 0) {
        int acc = 0;
#pragma unroll
        for (int e = 0; e < E_NUM; e++) { g_off[e] = acc; acc += g_cnt[e]; }
    }
}

// ---------------- grouped GEMMs (128x128x8 tile, 8x8 per thread) -----------
// C[m,n] = sum_k A[m,k]*B[n,k]   (both operands K-contiguous, row-major)

__global__ __launch_bounds__(256)
void up_kernel(const float* __restrict__ x,
               const float* __restrict__ w_up,
               const float* __restrict__ b_up) {
    int e   = blockIdx.z;
    int n_e = g_cnt[e];
    int m0  = blockIdx.y * 128;
    if (m0 >= n_e) return;
    int n0  = blockIdx.x * 128;

    const float* W = w_up + (size_t)e * U_DIM * D_DIM;

    __shared__ float As[8][128];
    __shared__ float Bs[8][128];

    int tid  = threadIdx.x;
    int lrow = tid >> 1;            // 0..127
    int lk   = (tid & 1) * 4;       // 0 or 4

    int  grow   = m0 + lrow;
    bool avalid = grow < n_e;
    int  tok    = avalid ? g_tok[e * T_TOK + grow] : 0;
    const float* arow = x + (size_t)tok * D_DIM;
    const float* brow = W + (size_t)(n0 + lrow) * D_DIM;

    float acc[8][8] = {};
    int tr = (tid >> 4) * 8;        // 0..120
    int tc = (tid & 15) * 8;        // 0..120

    for (int k0 = 0; k0 < D_DIM; k0 += 8) {
        float4 av = avalid ? *(const float4*)(arow + k0 + lk)
                           : make_float4(0.f, 0.f, 0.f, 0.f);
        float4 bv = *(const float4*)(brow + k0 + lk);
        __syncthreads();
        As[lk + 0][lrow] = av.x; As[lk + 1][lrow] = av.y;
        As[lk + 2][lrow] = av.z; As[lk + 3][lrow] = av.w;
        Bs[lk + 0][lrow] = bv.x; Bs[lk + 1][lrow] = bv.y;
        Bs[lk + 2][lrow] = bv.z; Bs[lk + 3][lrow] = bv.w;
        __syncthreads();
#pragma unroll
        for (int k = 0; k < 8; k++) {
            float a[8], b[8];
#pragma unroll
            for (int i = 0; i < 8; i++) a[i] = As[k][tr + i];
#pragma unroll
            for (int j = 0; j < 8; j++) b[j] = Bs[k][tc + j];
#pragma unroll
            for (int i = 0; i < 8; i++)
#pragma unroll
                for (int j = 0; j < 8; j++)
                    acc[i][j] += a[i] * b[j];
        }
    }

    // epilogue: bias + exact GELU -> H scratch
    int off = g_off[e];
    const float* bu = b_up + e * U_DIM;
#pragma unroll
    for (int i = 0; i < 8; i++) {
        int m = tr + i;
        if (m0 + m < n_e) {
            float* hp = g_H + (size_t)(off + m0 + m) * U_DIM + n0;
#pragma unroll
            for (int j = 0; j < 8; j++) {
                float v = acc[i][j] + bu[n0 + tc + j];
                v = 0.5f * v * (1.f + erff(v * 0.70710678118654752f));
                hp[tc + j] = v;
            }
        }
    }
}

__global__ __launch_bounds__(256)
void down_kernel(const float* __restrict__ w_down,
                 const float* __restrict__ b_down,
                 float* __restrict__ out) {
    int e   = blockIdx.z;
    int n_e = g_cnt[e];
    int m0  = blockIdx.y * 128;
    if (m0 >= n_e) return;
    int n0  = blockIdx.x * 128;
    int off = g_off[e];

    const float* W = w_down + (size_t)e * D_DIM * U_DIM;

    __shared__ float As[8][128];
    __shared__ float Bs[8][128];

    int tid  = threadIdx.x;
    int lrow = tid >> 1;
    int lk   = (tid & 1) * 4;

    int  grow   = m0 + lrow;
    bool avalid = grow < n_e;
    const float* arow = g_H + (size_t)(off + (avalid ? grow : 0)) * U_DIM;
    const float* brow = W + (size_t)(n0 + lrow) * U_DIM;

    float acc[8][8] = {};
    int tr = (tid >> 4) * 8;
    int tc = (tid & 15) * 8;

    for (int k0 = 0; k0 < U_DIM; k0 += 8) {
        float4 av = avalid ? *(const float4*)(arow + k0 + lk)
                           : make_float4(0.f, 0.f, 0.f, 0.f);
        float4 bv = *(const float4*)(brow + k0 + lk);
        __syncthreads();
        As[lk + 0][lrow] = av.x; As[lk + 1][lrow] = av.y;
        As[lk + 2][lrow] = av.z; As[lk + 3][lrow] = av.w;
        Bs[lk + 0][lrow] = bv.x; Bs[lk + 1][lrow] = bv.y;
        Bs[lk + 2][lrow] = bv.z; Bs[lk + 3][lrow] = bv.w;
        __syncthreads();
#pragma unroll
        for (int k = 0; k < 8; k++) {
            float a[8], b[8];
#pragma unroll
            for (int i = 0; i < 8; i++) a[i] = As[k][tr + i];
#pragma unroll
            for (int j = 0; j < 8; j++) b[j] = Bs[k][tc + j];
#pragma unroll
            for (int i = 0; i < 8; i++)
#pragma unroll
                for (int j = 0; j < 8; j++)
                    acc[i][j] += a[i] * b[j];
        }
    }

    // epilogue: bias, router weight, scatter-add into out
    const float* bd = b_down + e * D_DIM;
#pragma unroll
    for (int i = 0; i < 8; i++) {
        int m = tr + i;
        if (m0 + m < n_e) {
            int   tok = g_tok[e * T_TOK + m0 + m];
            float wgt = g_wt [e * T_TOK + m0 + m];
            float* op = out + (size_t)tok * D_DIM + n0;
#pragma unroll
            for (int j = 0; j < 8; j++) {
                float v = wgt * (acc[i][j] + bd[n0 + tc + j]);
                atomicAdd(&op[tc + j], v);
            }
        }
    }
}

// ---------------- launch ----------------------------------------------------
extern "C" void kernel_launch(void* const* d_in, const int* in_sizes, int n_in,
                              void* d_out, int out_size) {
    const float* x  = (const float*)d_in[0];
    const float* wr = (const float*)d_in[1];
    const float* wu = (const float*)d_in[2];
    const float* bu = (const float*)d_in[3];
    const float* wd = (const float*)d_in[4];
    const float* bd = (const float*)d_in[5];
    float* out = (float*)d_out;

    cudaMemsetAsync(out, 0, (size_t)out_size * sizeof(float), 0);
    zero_cnt_kernel<<<1, 32>>>();
    router_kernel<<<T_TOK / 4, 128>>>(x, wr);
    offsets_kernel<<<1, 32>>>();

    dim3 gu(U_DIM / 128, T_TOK / 128, E_NUM);   // (32, 32, 8), inactive tiles exit fast
    up_kernel<<<gu, 256>>>(x, wu, bu);

    dim3 gd(D_DIM / 128, T_TOK / 128, E_NUM);   // (8, 32, 8)
    down_kernel<<<gd, 256>>>(wd, bd, out);
}

// round 13
// speedup vs baseline: 3.1772x; 3.1727x over previous
#include <cuda_runtime.h>
#include <cuda_bf16.h>
#include <math.h>
#include <stdint.h>

// Problem constants
#define T_TOK 4096   // B*S tokens
#define D_DIM 1024   // embed dim
#define U_DIM 4096   // ffn dim
#define E_NUM 8      // experts

// ---------------- scratch (static device globals; no allocation) -----------
__device__ __nv_bfloat16 g_xh [(size_t)T_TOK * D_DIM];
__device__ __nv_bfloat16 g_xl [(size_t)T_TOK * D_DIM];
__device__ __nv_bfloat16 g_wuh[(size_t)E_NUM * U_DIM * D_DIM];
__device__ __nv_bfloat16 g_wul[(size_t)E_NUM * U_DIM * D_DIM];
__device__ __nv_bfloat16 g_wdh[(size_t)E_NUM * D_DIM * U_DIM];
__device__ __nv_bfloat16 g_wdl[(size_t)E_NUM * D_DIM * U_DIM];
__device__ __nv_bfloat16 g_Hh [(size_t)T_TOK * 2 * U_DIM];
__device__ __nv_bfloat16 g_Hl [(size_t)T_TOK * 2 * U_DIM];
__device__ int   g_tok[E_NUM * T_TOK];
__device__ float g_wt [E_NUM * T_TOK];
__device__ int   g_cnt[E_NUM];
__device__ int   g_off[E_NUM];

// ---------------- PTX helpers (baseline sm_80+ ISA only) -------------------
__device__ __forceinline__ uint32_t smem_u32(const void* p) {
    uint32_t a;
    asm("{ .reg .u64 t; cvta.to.shared.u64 t, %1; cvt.u32.u64 %0, t; }" : "=r"(a) : "l"(p));
    return a;
}

#define CP16(dst, src)  asm volatile("cp.async.cg.shared.global [%0], [%1], 16;" :: "r"(dst), "l"(src))
#define CP_COMMIT()     asm volatile("cp.async.commit_group;" ::: "memory")
#define CP_WAIT1()      asm volatile("cp.async.wait_group 1;" ::: "memory")
#define CP_WAIT0()      asm volatile("cp.async.wait_group 0;" ::: "memory")

#define LDSM4(r0, r1, r2, r3, addr) \
    asm volatile("ldmatrix.sync.aligned.m8n8.x4.shared.b16 {%0,%1,%2,%3}, [%4];" \
                 : "=r"(r0), "=r"(r1), "=r"(r2), "=r"(r3) : "r"(addr))

__device__ __forceinline__ void mma16816(float* d, const uint32_t* a, const uint32_t* b) {
    asm volatile(
        "mma.sync.aligned.m16n8k16.row.col.f32.bf16.bf16.f32 "
        "{%0,%1,%2,%3}, {%4,%5,%6,%7}, {%8,%9}, {%0,%1,%2,%3};"
        : "+f"(d[0]), "+f"(d[1]), "+f"(d[2]), "+f"(d[3])
        : "r"(a[0]), "r"(a[1]), "r"(a[2]), "r"(a[3]), "r"(b[0]), "r"(b[1]));
}

// SMEM tile: 128 rows x 4 chunks of 16B (BK=32 bf16). XOR swizzle keeps
// ldmatrix 8-row reads on distinct banks: chunk' = chunk ^ ((row>>1)&3).
__device__ __forceinline__ uint32_t tile_off(int row, int chunk) {
    return (uint32_t)(row * 64 + ((chunk ^ ((row >> 1) & 3)) << 4));
}

__device__ __forceinline__ float gelu_exact(float v) {
    return 0.5f * v * (1.f + erff(v * 0.70710678118654752f));
}
__device__ __forceinline__ void split_bf16(float v, __nv_bfloat16& h, __nv_bfloat16& l) {
    h = __float2bfloat16_rn(v);
    l = __float2bfloat16_rn(v - __bfloat162float(h));
}

// ---------------- input split: fp32 -> bf16 hi + bf16 lo -------------------
__global__ void split_kernel(const float* __restrict__ src,
                             __nv_bfloat16* __restrict__ hi,
                             __nv_bfloat16* __restrict__ lo, int n) {
    int stride = gridDim.x * blockDim.x * 4;
    for (int i = (blockIdx.x * blockDim.x + threadIdx.x) * 4; i < n; i += stride) {
        float4 v = *(const float4*)(src + i);
        __nv_bfloat16 h0, h1, h2, h3, l0, l1, l2, l3;
        split_bf16(v.x, h0, l0); split_bf16(v.y, h1, l1);
        split_bf16(v.z, h2, l2); split_bf16(v.w, h3, l3);
        *(__nv_bfloat162*)(hi + i)     = __halves2bfloat162(h0, h1);
        *(__nv_bfloat162*)(hi + i + 2) = __halves2bfloat162(h2, h3);
        *(__nv_bfloat162*)(lo + i)     = __halves2bfloat162(l0, l1);
        *(__nv_bfloat162*)(lo + i + 2) = __halves2bfloat162(l2, l3);
    }
}

// ---------------- router ----------------------------------------------------
__global__ void zero_cnt_kernel() {
    if (threadIdx.x < E_NUM) g_cnt[threadIdx.x] = 0;
}

__global__ void router_kernel(const float* __restrict__ x,
                              const float* __restrict__ wr) {
    int t    = blockIdx.x * 4 + (threadIdx.x >> 5);
    int lane = threadIdx.x & 31;
    if (t >= T_TOK) return;
    const float* xr = x + (size_t)t * D_DIM;

    float logit[E_NUM];
#pragma unroll
    for (int e = 0; e < E_NUM; e++) {
        const float* w = wr + e * D_DIM;
        float s = 0.f;
        for (int i = lane; i < D_DIM; i += 32)
            s += xr[i] * w[i];
#pragma unroll
        for (int o = 16; o > 0; o >>= 1)
            s += __shfl_xor_sync(0xffffffffu, s, o);
        logit[e] = s;
    }

    if (lane == 0) {
        int e0 = 0; float l0 = logit[0];
#pragma unroll
        for (int e = 1; e < E_NUM; e++)
            if (logit[e] > l0) { l0 = logit[e]; e0 = e; }
        int e1 = -1; float l1 = -INFINITY;
#pragma unroll
        for (int e = 0; e < E_NUM; e++)
            if (e != e0 && logit[e] > l1) { l1 = logit[e]; e1 = e; }

        float p1 = expf(l1 - l0);
        float inv = 1.f / (1.f + p1);
        float w0 = inv, w1 = p1 * inv;

        int p;
        p = atomicAdd(&g_cnt[e0], 1);
        g_tok[e0 * T_TOK + p] = t;  g_wt[e0 * T_TOK + p] = w0;
        p = atomicAdd(&g_cnt[e1], 1);
        g_tok[e1 * T_TOK + p] = t;  g_wt[e1 * T_TOK + p] = w1;
    }
}

__global__ void offsets_kernel() {
    if (threadIdx.x == 0) {
        int acc = 0;
#pragma unroll
        for (int e = 0; e < E_NUM; e++) { g_off[e] = acc; acc += g_cnt[e]; }
    }
}

// ---------------- grouped GEMM: mma.sync bf16, 3-pass hi/lo split ----------
// C[m,n] = sum_k A[m,k]*B[n,k], A gathered (up: tokens, down: H rows).
// Tile BM=128, BN=128, BK=32; 8 warps each compute 32(M) x 64(N).
// SMEM layout: [s_tok 512B][s_wt 512B][stage0: Ah 8K|Al 8K|Bh 8K|Bl 8K][stage1 ...]

static constexpr int SMEM_TILES = 1024;
static constexpr int STAGE_BYTES = 32768;
static constexpr int SMEM_BYTES = SMEM_TILES + 2 * STAGE_BYTES;  // 66560

template<int KDIM, bool IS_UP>
__global__ void __launch_bounds__(256, 2)
moe_mma(const __nv_bfloat16* __restrict__ Ah, const __nv_bfloat16* __restrict__ Al,
        const __nv_bfloat16* __restrict__ Wh, const __nv_bfloat16* __restrict__ Wl,
        const float* __restrict__ bias, float* __restrict__ out)
{
    constexpr int NTOT = IS_UP ? U_DIM : D_DIM;
    constexpr int NT   = KDIM / 32;

    int e   = blockIdx.z;
    int n_e = g_cnt[e];
    int m0  = blockIdx.y * 128;
    if (m0 >= n_e) return;
    int n0  = blockIdx.x * 128;
    int off = g_off[e];

    int tid  = threadIdx.x;
    int lane = tid & 31;
    int wid  = tid >> 5;
    int wm   = (wid & 3) * 32;   // warp M offset (0..96)
    int wn   = (wid >> 2) * 64;  // warp N offset (0 or 64)

    extern __shared__ __align__(16) char smem[];
    uint32_t sb = smem_u32(smem);
    int*   s_tok = (int*)(smem);
    float* s_wt  = (float*)(smem + 512);

    if (tid < 128) {
        int grow = m0 + tid;
        int idx  = e * T_TOK + (grow < n_e ? grow : n_e - 1);
        s_tok[tid] = g_tok[idx];
        s_wt[tid]  = g_wt[idx];
    }
    __syncthreads();

    // ---- per-thread cp.async slots: 2 (row,chunk) pairs, reused for 4 tiles
    int c    = tid & 3;            // 16B chunk within 64B row
    int row0 = tid >> 2;           // 0..63
    int row1 = row0 + 64;          // 64..127
    uint32_t dst0 = tile_off(row0, c);
    uint32_t dst1 = tile_off(row1, c);

    const __nv_bfloat16 *aH0, *aH1, *aL0, *aL1;
    if (IS_UP) {
        aH0 = Ah + (size_t)s_tok[row0] * KDIM + c * 8;
        aH1 = Ah + (size_t)s_tok[row1] * KDIM + c * 8;
        aL0 = Al + (size_t)s_tok[row0] * KDIM + c * 8;
        aL1 = Al + (size_t)s_tok[row1] * KDIM + c * 8;
    } else {
        int r0c = m0 + row0; if (r0c >= n_e) r0c = n_e - 1;
        int r1c = m0 + row1; if (r1c >= n_e) r1c = n_e - 1;
        aH0 = Ah + (size_t)(off + r0c) * KDIM + c * 8;
        aH1 = Ah + (size_t)(off + r1c) * KDIM + c * 8;
        aL0 = Al + (size_t)(off + r0c) * KDIM + c * 8;
        aL1 = Al + (size_t)(off + r1c) * KDIM + c * 8;
    }
    const __nv_bfloat16* We_h = Wh + (size_t)e * NTOT * KDIM;
    const __nv_bfloat16* We_l = Wl + (size_t)e * NTOT * KDIM;
    const __nv_bfloat16* bH0 = We_h + (size_t)(n0 + row0) * KDIM + c * 8;
    const __nv_bfloat16* bH1 = We_h + (size_t)(n0 + row1) * KDIM + c * 8;
    const __nv_bfloat16* bL0 = We_l + (size_t)(n0 + row0) * KDIM + c * 8;
    const __nv_bfloat16* bL1 = We_l + (size_t)(n0 + row1) * KDIM + c * 8;

    auto load_stage = [&](int kt, int s) {
        uint32_t tb = sb + SMEM_TILES + s * STAGE_BYTES;
        int ko = kt * 32;
        CP16(tb +         dst0, aH0 + ko);  CP16(tb +         dst1, aH1 + ko);
        CP16(tb +  8192 + dst0, aL0 + ko);  CP16(tb +  8192 + dst1, aL1 + ko);
        CP16(tb + 16384 + dst0, bH0 + ko);  CP16(tb + 16384 + dst1, bH1 + ko);
        CP16(tb + 24576 + dst0, bL0 + ko);  CP16(tb + 24576 + dst1, bL1 + ko);
        CP_COMMIT();
    };

    // ---- ldmatrix address components (fixed per thread)
    int arow = wm + (lane & 15);            // + mi*16
    int achk = lane >> 4;                   // + ks*2
    int brow = wn + ((lane >> 4) << 3) + (lane & 7);   // + np*16
    int bchk = (lane >> 3) & 1;             // + ks*2

    float acc[2][8][4] = {};

    load_stage(0, 0);
    for (int kt = 0; kt < NT; kt++) {
        int s = kt & 1;
        if (kt + 1 < NT) { load_stage(kt + 1, s ^ 1); CP_WAIT1(); }
        else             { CP_WAIT0(); }
        __syncthreads();

        uint32_t tb = sb + SMEM_TILES + s * STAGE_BYTES;
#pragma unroll
        for (int ks = 0; ks < 2; ks++) {
            uint32_t aHf[2][4], aLf[2][4];
#pragma unroll
            for (int mi = 0; mi < 2; mi++) {
                uint32_t ao = tile_off(arow + mi * 16, ks * 2 + achk);
                LDSM4(aHf[mi][0], aHf[mi][1], aHf[mi][2], aHf[mi][3], tb + ao);
                LDSM4(aLf[mi][0], aLf[mi][1], aLf[mi][2], aLf[mi][3], tb + 8192 + ao);
            }
#pragma unroll
            for (int np = 0; np < 4; np++) {
                uint32_t bo = tile_off(brow + np * 16, ks * 2 + bchk);
                uint32_t bHf[4], bLf[4];
                LDSM4(bHf[0], bHf[1], bHf[2], bHf[3], tb + 16384 + bo);
                LDSM4(bLf[0], bLf[1], bLf[2], bLf[3], tb + 24576 + bo);
#pragma unroll
                for (int mi = 0; mi < 2; mi++) {
#pragma unroll
                    for (int sub = 0; sub < 2; sub++) {
                        float* d = acc[mi][np * 2 + sub];
                        mma16816(d, aHf[mi], &bHf[sub * 2]);   // hi*hi
                        mma16816(d, aHf[mi], &bLf[sub * 2]);   // hi*lo
                        mma16816(d, aLf[mi], &bHf[sub * 2]);   // lo*hi
                    }
                }
            }
        }
        __syncthreads();
    }

    // ---- epilogue. acc[mi][nf]: {c0,c1}=row r, cols 2q,+1; {c2,c3}=row r+8
    int r = lane >> 2, q = lane & 3;
    const float* brow_bias = bias + (size_t)e * NTOT;
#pragma unroll
    for (int mi = 0; mi < 2; mi++) {
#pragma unroll
        for (int nf = 0; nf < 8; nf++) {
            float* a4 = acc[mi][nf];
            int col  = n0 + wn + nf * 8 + 2 * q;
            float bz0 = brow_bias[col], bz1 = brow_bias[col + 1];
#pragma unroll
            for (int h = 0; h < 2; h++) {
                int local = wm + mi * 16 + r + h * 8;
                if (m0 + local >= n_e) continue;
                float v0 = a4[h * 2 + 0] + bz0;
                float v1 = a4[h * 2 + 1] + bz1;
                if (IS_UP) {
                    v0 = gelu_exact(v0); v1 = gelu_exact(v1);
                    __nv_bfloat16 h0, h1, l0, l1;
                    split_bf16(v0, h0, l0); split_bf16(v1, h1, l1);
                    size_t o = (size_t)(off + m0 + local) * U_DIM + col;
                    *(__nv_bfloat162*)(g_Hh + o) = __halves2bfloat162(h0, h1);
                    *(__nv_bfloat162*)(g_Hl + o) = __halves2bfloat162(l0, l1);
                } else {
                    int   tok = s_tok[local];
                    float wgt = s_wt[local];
                    float* op = out + (size_t)tok * D_DIM + col;
                    atomicAdd(op,     wgt * v0);
                    atomicAdd(op + 1, wgt * v1);
                }
            }
        }
    }
}

// ---------------- launch -----------------------------------------------------
extern "C" void kernel_launch(void* const* d_in, const int* in_sizes, int n_in,
                              void* d_out, int out_size) {
    const float* x  = (const float*)d_in[0];
    const float* wr = (const float*)d_in[1];
    const float* wu = (const float*)d_in[2];
    const float* bu = (const float*)d_in[3];
    const float* wd = (const float*)d_in[4];
    const float* bd = (const float*)d_in[5];
    float* out = (float*)d_out;

    cudaFuncSetAttribute(moe_mma<D_DIM, true>,
                         cudaFuncAttributeMaxDynamicSharedMemorySize, SMEM_BYTES);
    cudaFuncSetAttribute(moe_mma<U_DIM, false>,
                         cudaFuncAttributeMaxDynamicSharedMemorySize, SMEM_BYTES);

    __nv_bfloat16 *xh, *xl, *wuh, *wul, *wdh, *wdl, *Hh, *Hl;
    cudaGetSymbolAddress((void**)&xh,  g_xh);
    cudaGetSymbolAddress((void**)&xl,  g_xl);
    cudaGetSymbolAddress((void**)&wuh, g_wuh);
    cudaGetSymbolAddress((void**)&wul, g_wul);
    cudaGetSymbolAddress((void**)&wdh, g_wdh);
    cudaGetSymbolAddress((void**)&wdl, g_wdl);
    cudaGetSymbolAddress((void**)&Hh,  g_Hh);
    cudaGetSymbolAddress((void**)&Hl,  g_Hl);

    cudaMemsetAsync(out, 0, (size_t)out_size * sizeof(float), 0);
    zero_cnt_kernel<<<1, 32>>>();
    router_kernel<<<T_TOK / 4, 128>>>(x, wr);
    offsets_kernel<<<1, 32>>>();

    // fp32 -> bf16 hi/lo splits
    int n_x = T_TOK * D_DIM, n_w = E_NUM * U_DIM * D_DIM;
    split_kernel<<<2048,  256>>>(x,  xh,  xl,  n_x);
    split_kernel<<<16384, 256>>>(wu, wuh, wul, n_w);
    split_kernel<<<16384, 256>>>(wd, wdh, wdl, n_w);

    // up: M=8192 routed rows, N=4096, K=1024
    moe_mma<D_DIM, true><<<dim3(U_DIM / 128, T_TOK / 128, E_NUM), 256, SMEM_BYTES>>>(
        xh, xl, wuh, wul, bu, nullptr);
    // down: M=8192 routed rows, N=1024, K=4096
    moe_mma<U_DIM, false><<<dim3(D_DIM / 128, T_TOK / 128, E_NUM), 256, SMEM_BYTES>>>(
        Hh, Hl, wdh, wdl, bd, out);
}